// round 3
// baseline (speedup 1.0000x reference)
#include <cuda_runtime.h>
#include <cstdint>

#define NH    16
#define NK    8
#define D_IN  1024
#define D_H   64
#define D_O   64
#define MT    128

// scratch for scores (allocation-free rule: __device__ global)
__device__ float g_scores[8192 * NK];

__device__ __forceinline__ unsigned long long fma2(unsigned long long a,
                                                   unsigned long long b,
                                                   unsigned long long c) {
    unsigned long long d;
    asm("fma.rn.f32x2 %0, %1, %2, %3;" : "=l"(d) : "l"(a), "l"(b), "l"(c));
    return d;
}
__device__ __forceinline__ unsigned long long add2(unsigned long long a,
                                                   unsigned long long b) {
    unsigned long long d;
    asm("add.rn.f32x2 %0, %1, %2;" : "=l"(d) : "l"(a), "l"(b));
    return d;
}
__device__ __forceinline__ unsigned long long splat2(float x) {
    unsigned long long d;
    asm("mov.b64 %0, {%1, %1};" : "=l"(d) : "f"(x));
    return d;
}

// ---------------------------------------------------------------------------
// Kernel 1: scores[m,k] = phi[t,k] + sum_i x[m,i] * diag[k,i]
// 1 warp per token, 8 tokens per 256-thread block.
// ---------------------------------------------------------------------------
__global__ __launch_bounds__(256) void scores_kernel(
        const float* __restrict__ x,
        const float* __restrict__ diag,
        const float* __restrict__ phi,
        int M, int T) {
    __shared__ float sdiag[NK * D_IN];
    int tid = threadIdx.x;
    for (int idx = tid; idx < NK * D_IN / 4; idx += 256)
        ((float4*)sdiag)[idx] = ((const float4*)diag)[idx];
    __syncthreads();

    int warp = tid >> 5, lane = tid & 31;
    int m = blockIdx.x * 8 + warp;
    if (m >= M) return;

    const float4* xr = (const float4*)(x + (size_t)m * D_IN);
    float acc[NK];
#pragma unroll
    for (int k = 0; k < NK; k++) acc[k] = 0.f;

#pragma unroll
    for (int j = 0; j < 8; j++) {
        float4 xv = xr[j * 32 + lane];
#pragma unroll
        for (int k = 0; k < NK; k++) {
            float4 dv = *(const float4*)&sdiag[k * D_IN + j * 128 + lane * 4];
            acc[k] += xv.x * dv.x + xv.y * dv.y + xv.z * dv.z + xv.w * dv.w;
        }
    }
#pragma unroll
    for (int k = 0; k < NK; k++) {
#pragma unroll
        for (int off = 16; off; off >>= 1)
            acc[k] += __shfl_xor_sync(0xffffffffu, acc[k], off);
    }
    if (lane < NK) {
        float v = 0.f;
#pragma unroll
        for (int k = 0; k < NK; k++)
            if (lane == k) v = acc[k];
        int t = m % T;
        g_scores[m * NK + lane] = phi[t * NK + lane] + v;
    }
}

// ---------------------------------------------------------------------------
// Kernel 2: per (128-token tile, head) block, 256 threads.
// Thread (r, half) : r = tid>>1 (row), half = tid&1 (i-half of 32).
//   out[m0+r][h*64+o] = sum_k sum_i (s[r,k]*x[r,i]) * W[h][k][i][o]
// A (s-folded x) lives in registers; B rows broadcast from smem (2 distinct
// addresses per LDS phase); 32 f32x2 accumulators cover all 64 outputs
// (partial over the thread's i-half); cross-half combine via shfl_xor(1).
// smem: W[h] verbatim [k][i][o] = 128 KB (no transform needed).
// ---------------------------------------------------------------------------
#define WS_FLOATS  (NK * D_H * D_O)          /* 32768 */
#define SMEM_BYTES (WS_FLOATS * 4)           /* 131072 */

__global__ __launch_bounds__(256, 1) void main_kernel(
        const float* __restrict__ x,
        const float* __restrict__ weight,
        float* __restrict__ out) {
    extern __shared__ float Ws[];            // [k][i][o] verbatim
    int tid = threadIdx.x;
    int h   = blockIdx.y;
    int m0  = blockIdx.x * MT;

    // --- fill W[h] (layout already [k][i][o] contiguous)
    {
        const float4* wg = (const float4*)(weight + (size_t)h * WS_FLOATS);
        for (int idx = tid; idx < WS_FLOATS / 4; idx += 256)
            ((float4*)Ws)[idx] = wg[idx];
    }

    int r = tid >> 1, half = tid & 1;

    // --- per-thread x half-row + row scores (direct from gmem)
    float xr[32];
    {
        const float4* xp = (const float4*)(x + (size_t)(m0 + r) * D_IN
                                           + h * D_H + half * 32);
#pragma unroll
        for (int j = 0; j < 8; j++) ((float4*)xr)[j] = xp[j];
    }
    float sr[NK];
    {
        const float4* sp = (const float4*)(g_scores + (size_t)(m0 + r) * NK);
        ((float4*)sr)[0] = sp[0];
        ((float4*)sr)[1] = sp[1];
    }
    __syncthreads();

    unsigned long long acc[32];
#pragma unroll
    for (int c = 0; c < 32; c++) acc[c] = 0ull;

#pragma unroll 1
    for (int k = 0; k < NK; k++) {
        const float* bp = Ws + ((k << 6) + (half << 5)) * 64;
        float sk = sr[k];
#pragma unroll 4
        for (int i = 0; i < 32; i++) {
            unsigned long long av = splat2(sk * xr[i]);
            const ulonglong2* bq = (const ulonglong2*)(bp + (i << 6));
#pragma unroll
            for (int c = 0; c < 16; c++) {
                ulonglong2 b = bq[c];
                acc[c * 2]     = fma2(av, b.x, acc[c * 2]);
                acc[c * 2 + 1] = fma2(av, b.y, acc[c * 2 + 1]);
            }
        }
    }

    // --- combine the two i-halves (lanes differ by 1)
#pragma unroll
    for (int c = 0; c < 32; c++) {
        unsigned long long o = __shfl_xor_sync(0xffffffffu, acc[c], 1);
        acc[c] = add2(acc[c], o);
    }

    // --- store: even lane -> cols 0..31, odd lane -> cols 32..63
    {
        float* op = out + (size_t)(m0 + r) * D_IN + h * D_H + half * 32;
        int base = half * 16;
#pragma unroll
        for (int q = 0; q < 8; q++) {
            ulonglong2 v;
            v.x = acc[base + q * 2];
            v.y = acc[base + q * 2 + 1];
            ((ulonglong2*)op)[q] = v;
        }
    }
}

// ---------------------------------------------------------------------------
extern "C" void kernel_launch(void* const* d_in, const int* in_sizes, int n_in,
                              void* d_out, int out_size) {
    const float* x      = (const float*)d_in[0];
    const float* weight = (const float*)d_in[1];
    const float* diag   = (const float*)d_in[2];
    const float* phi    = (const float*)d_in[3];
    float* out          = (float*)d_out;

    int M = in_sizes[0] / D_IN;   // B*T tokens
    int T = in_sizes[3] / NK;     // phi rows

    cudaFuncSetAttribute(main_kernel,
                         cudaFuncAttributeMaxDynamicSharedMemorySize, SMEM_BYTES);

    scores_kernel<<<(M + 7) / 8, 256>>>(x, diag, phi, M, T);

    dim3 grid(M / MT, NH);
    main_kernel<<<grid, 256, SMEM_BYTES>>>(x, weight, out);
}

// round 4
// speedup vs baseline: 4.6994x; 4.6994x over previous
#include <cuda_runtime.h>
#include <cuda_bf16.h>
#include <cstdint>

#define NH    16
#define NK    8
#define D_IN  1024
#define D_H   64
#define MT    128
#define BROW  72          /* padded B/A row length in b16 units (144 B) */

// scratch (allocation-free rule: __device__ globals)
__device__ float         g_scores[8192 * NK];
__device__ __nv_bfloat16 g_bhi[NH * NK * 64 * BROW];   // [h][c][o][72] (B^T, padded)
__device__ __nv_bfloat16 g_blo[NH * NK * 64 * BROW];

__device__ __forceinline__ uint32_t smem_u32(const void* p) {
    uint32_t a;
    asm("{ .reg .u64 t; cvta.to.shared.u64 t, %1; cvt.u32.u64 %0, t; }" : "=r"(a) : "l"(p));
    return a;
}
__device__ __forceinline__ void ldmx4(uint32_t* r, const void* p) {
    uint32_t a = smem_u32(p);
    asm volatile("ldmatrix.sync.aligned.m8n8.x4.shared.b16 {%0,%1,%2,%3}, [%4];"
                 : "=r"(r[0]), "=r"(r[1]), "=r"(r[2]), "=r"(r[3]) : "r"(a));
}
__device__ __forceinline__ void mma16816(float* d, const uint32_t* a, const uint32_t* b) {
    asm volatile("mma.sync.aligned.m16n8k16.row.col.f32.bf16.bf16.f32 "
                 "{%0,%1,%2,%3}, {%4,%5,%6,%7}, {%8,%9}, {%0,%1,%2,%3};"
                 : "+f"(d[0]), "+f"(d[1]), "+f"(d[2]), "+f"(d[3])
                 : "r"(a[0]), "r"(a[1]), "r"(a[2]), "r"(a[3]), "r"(b[0]), "r"(b[1]));
}

// ---------------------------------------------------------------------------
// Prep: per (h,c): B^T hi/lo with 144B-padded rows.  g_b*[((h*8+c)*64+o)*72+i]
// ---------------------------------------------------------------------------
__global__ __launch_bounds__(256) void wsplit_kernel(const float* __restrict__ w) {
    __shared__ float sw[64 * 64];
    int hc = blockIdx.x;                       // h*NK + c
    const float4* wg = (const float4*)(w + (size_t)hc * 4096);
    for (int idx = threadIdx.x; idx < 1024; idx += 256)
        ((float4*)sw)[idx] = wg[idx];
    __syncthreads();

    int o = threadIdx.x >> 2, q = threadIdx.x & 3;   // q = i-quarter of 16
    __nv_bfloat16 hi[16], lo[16];
#pragma unroll
    for (int j = 0; j < 16; j++) {
        float v = sw[(q * 16 + j) * 64 + o];          // w[h][c][i][o]
        __nv_bfloat16 hb = __float2bfloat16_rn(v);
        hi[j] = hb;
        lo[j] = __float2bfloat16_rn(v - __bfloat162float(hb));
    }
    size_t base = ((size_t)hc * 64 + o) * BROW + q * 16;
    *(uint4*)(g_bhi + base)     = ((uint4*)hi)[0];
    *(uint4*)(g_bhi + base + 8) = ((uint4*)hi)[1];
    *(uint4*)(g_blo + base)     = ((uint4*)lo)[0];
    *(uint4*)(g_blo + base + 8) = ((uint4*)lo)[1];
}

// ---------------------------------------------------------------------------
// Kernel 1: scores[m,k] = phi[t,k] + sum_i x[m,i] * diag[k,i]
// ---------------------------------------------------------------------------
__global__ __launch_bounds__(256) void scores_kernel(
        const float* __restrict__ x, const float* __restrict__ diag,
        const float* __restrict__ phi, int M, int T) {
    __shared__ float sdiag[NK * D_IN];
    int tid = threadIdx.x;
    for (int idx = tid; idx < NK * D_IN / 4; idx += 256)
        ((float4*)sdiag)[idx] = ((const float4*)diag)[idx];
    __syncthreads();

    int warp = tid >> 5, lane = tid & 31;
    int m = blockIdx.x * 8 + warp;
    if (m >= M) return;

    const float4* xr = (const float4*)(x + (size_t)m * D_IN);
    float acc[NK];
#pragma unroll
    for (int k = 0; k < NK; k++) acc[k] = 0.f;
#pragma unroll
    for (int j = 0; j < 8; j++) {
        float4 xv = xr[j * 32 + lane];
#pragma unroll
        for (int k = 0; k < NK; k++) {
            float4 dv = *(const float4*)&sdiag[k * D_IN + j * 128 + lane * 4];
            acc[k] += xv.x * dv.x + xv.y * dv.y + xv.z * dv.z + xv.w * dv.w;
        }
    }
#pragma unroll
    for (int k = 0; k < NK; k++)
#pragma unroll
        for (int off = 16; off; off >>= 1)
            acc[k] += __shfl_xor_sync(0xffffffffu, acc[k], off);
    if (lane < NK) {
        float v = 0.f;
#pragma unroll
        for (int k = 0; k < NK; k++)
            if (lane == k) v = acc[k];
        int t = m % T;
        g_scores[m * NK + lane] = phi[t * NK + lane] + v;
    }
}

// ---------------------------------------------------------------------------
// Main kernel: per (128-token tile, head). 256 threads, 8 warps =
// 4 m-groups(32 rows) x 2 n-halves(32 cols). 3-pass bf16-split mma.sync.
// smem: B hi/lo (all 8 chunks, padded) 144KB + A hi/lo (1 chunk) 36KB.
// ---------------------------------------------------------------------------
#define SB_HI   0
#define SB_LO   73728
#define SA_HI   147456
#define SA_LO   165888
#define SMEM_TOTAL 184320

__global__ __launch_bounds__(256, 1) void main_kernel(
        const float* __restrict__ x, float* __restrict__ out) {
    extern __shared__ char sm[];
    char* Bh = sm + SB_HI;   // [c][o][72] b16
    char* Bl = sm + SB_LO;
    char* Ah = sm + SA_HI;   // [r][72] b16
    char* Al = sm + SA_LO;

    int tid = threadIdx.x;
    int h   = blockIdx.y;
    int m0  = blockIdx.x * MT;

    // --- copy B hi/lo for this head (contiguous, coalesced)
    {
        const uint4* gh = (const uint4*)(g_bhi + (size_t)h * NK * 64 * BROW);
        const uint4* gl = (const uint4*)(g_blo + (size_t)h * NK * 64 * BROW);
        uint4* dh = (uint4*)Bh;
        uint4* dl = (uint4*)Bl;
        for (int i = tid; i < NK * 64 * BROW / 8; i += 256) {
            dh[i] = gh[i];
            dl[i] = gl[i];
        }
    }

    // --- per-thread x half-row + scores (registers)
    int r = tid >> 1, half = tid & 1;
    float xr[32];
    {
        const float4* xp = (const float4*)(x + (size_t)(m0 + r) * D_IN
                                           + h * D_H + half * 32);
#pragma unroll
        for (int j = 0; j < 8; j++) ((float4*)xr)[j] = xp[j];
    }
    float sr[NK];
    {
        const float4* sp = (const float4*)(g_scores + (size_t)(m0 + r) * NK);
        ((float4*)sr)[0] = sp[0];
        ((float4*)sr)[1] = sp[1];
    }

    int lane = tid & 31, wid = tid >> 5;
    int wm = wid >> 1, wn = wid & 1;

    float acc[2][4][4];
#pragma unroll
    for (int a = 0; a < 2; a++)
#pragma unroll
        for (int b = 0; b < 4; b++)
#pragma unroll
            for (int cc = 0; cc < 4; cc++) acc[a][b][cc] = 0.f;

    // ldmatrix lane-address components
    int a_r  = (lane & 15);          // row within 16
    int a_c  = (lane >> 4) * 16;     // +16B for k8 tiles
    int b_r  = (lane & 7) + ((lane >> 4) & 1) * 8;   // n row within 16
    int b_c  = ((lane >> 3) & 1) * 16;               // +16B for k8 tiles

#pragma unroll 1
    for (int c = 0; c < NK; c++) {
        __syncthreads();   // A buffer free (and B copy visible on c==0)

        // --- build A' chunk: hi/lo of s*x
        {
            float s = sr[c];
            uint32_t hi[16], lo[16];
#pragma unroll
            for (int j = 0; j < 16; j++) {
                float v0 = s * xr[2 * j], v1 = s * xr[2 * j + 1];
                __nv_bfloat162 hh = __floats2bfloat162_rn(v0, v1);
                float l0 = v0 - __bfloat162float(hh.x);
                float l1 = v1 - __bfloat162float(hh.y);
                __nv_bfloat162 ll = __floats2bfloat162_rn(l0, l1);
                hi[j] = *(uint32_t*)&hh;
                lo[j] = *(uint32_t*)&ll;
            }
            char* pa = Ah + r * 144 + half * 64;
            char* pb = Al + r * 144 + half * 64;
#pragma unroll
            for (int q = 0; q < 4; q++) {
                ((uint4*)pa)[q] = ((uint4*)hi)[q];
                ((uint4*)pb)[q] = ((uint4*)lo)[q];
            }
        }
        __syncthreads();

        // --- mma over this chunk (4 k16 steps)
        const char* bc_h = Bh + c * 9216;
        const char* bc_l = Bl + c * 9216;
#pragma unroll 1
        for (int ks = 0; ks < 4; ks++) {
            uint32_t ahi[8], alo[8];
            const char* pah = Ah + (wm * 32 + a_r) * 144 + ks * 32 + a_c;
            const char* pal = Al + (wm * 32 + a_r) * 144 + ks * 32 + a_c;
            ldmx4(ahi,     pah);
            ldmx4(ahi + 4, pah + 16 * 144);
            ldmx4(alo,     pal);
            ldmx4(alo + 4, pal + 16 * 144);
#pragma unroll
            for (int p = 0; p < 2; p++) {
                uint32_t bhi[4], blo[4];
                int brow = wn * 32 + p * 16 + b_r;
                ldmx4(bhi, bc_h + brow * 144 + ks * 32 + b_c);
                ldmx4(blo, bc_l + brow * 144 + ks * 32 + b_c);
#pragma unroll
                for (int mb = 0; mb < 2; mb++)
#pragma unroll
                    for (int nb = 0; nb < 2; nb++) {
                        float* d = acc[mb][p * 2 + nb];
                        mma16816(d, ahi + mb * 4, bhi + nb * 2);   // hi*hi
                        mma16816(d, ahi + mb * 4, blo + nb * 2);   // hi*lo
                        mma16816(d, alo + mb * 4, bhi + nb * 2);   // lo*hi
                    }
            }
        }
    }

    // --- epilogue: fragment d -> out
#pragma unroll
    for (int mb = 0; mb < 2; mb++) {
        int m = m0 + wm * 32 + mb * 16 + (lane >> 2);
        float* o0 = out + (size_t)m * D_IN + h * D_H + wn * 32 + (lane & 3) * 2;
#pragma unroll
        for (int nb = 0; nb < 4; nb++) {
            float2 v0 = make_float2(acc[mb][nb][0], acc[mb][nb][1]);
            float2 v1 = make_float2(acc[mb][nb][2], acc[mb][nb][3]);
            *(float2*)(o0 + nb * 8)                 = v0;
            *(float2*)(o0 + nb * 8 + 8 * (size_t)D_IN) = v1;
        }
    }
}

// ---------------------------------------------------------------------------
extern "C" void kernel_launch(void* const* d_in, const int* in_sizes, int n_in,
                              void* d_out, int out_size) {
    const float* x      = (const float*)d_in[0];
    const float* weight = (const float*)d_in[1];
    const float* diag   = (const float*)d_in[2];
    const float* phi    = (const float*)d_in[3];
    float* out          = (float*)d_out;

    int M = in_sizes[0] / D_IN;   // B*T tokens
    int T = in_sizes[3] / NK;     // phi rows

    cudaFuncSetAttribute(main_kernel,
                         cudaFuncAttributeMaxDynamicSharedMemorySize, SMEM_TOTAL);

    wsplit_kernel<<<NH * NK, 256>>>(weight);
    scores_kernel<<<(M + 7) / 8, 256>>>(x, diag, phi, M, T);

    dim3 grid(M / MT, NH);
    main_kernel<<<grid, 256, SMEM_TOTAL>>>(x, out);
}

// round 5
// speedup vs baseline: 5.5797x; 1.1873x over previous
#include <cuda_runtime.h>
#include <cuda_bf16.h>
#include <cstdint>

#define NH    16
#define NK    8
#define D_IN  1024
#define D_H   64
#define MT    256

// scratch (allocation-free rule: __device__ globals)
__device__ float         g_scores[8192 * NK];
__device__ __nv_bfloat16 g_bhi[NH * NK * 64 * 64];   // [h][c][o][i]  (B^T rows, 128B)
__device__ __nv_bfloat16 g_blo[NH * NK * 64 * 64];

__device__ __forceinline__ uint32_t smem_u32(const void* p) {
    uint32_t a;
    asm("{ .reg .u64 t; cvta.to.shared.u64 t, %1; cvt.u32.u64 %0, t; }" : "=r"(a) : "l"(p));
    return a;
}
__device__ __forceinline__ void ldmx4(uint32_t* r, uint32_t a) {
    asm volatile("ldmatrix.sync.aligned.m8n8.x4.shared.b16 {%0,%1,%2,%3}, [%4];"
                 : "=r"(r[0]), "=r"(r[1]), "=r"(r[2]), "=r"(r[3]) : "r"(a));
}
__device__ __forceinline__ void mma16816(float* d, const uint32_t* a, const uint32_t* b) {
    asm volatile("mma.sync.aligned.m16n8k16.row.col.f32.bf16.bf16.f32 "
                 "{%0,%1,%2,%3}, {%4,%5,%6,%7}, {%8,%9}, {%0,%1,%2,%3};"
                 : "+f"(d[0]), "+f"(d[1]), "+f"(d[2]), "+f"(d[3])
                 : "r"(a[0]), "r"(a[1]), "r"(a[2]), "r"(a[3]), "r"(b[0]), "r"(b[1]));
}

// ---------------------------------------------------------------------------
// Prep: B^T hi/lo, unpadded 128B rows: g_b*[((h*8+c)*64+o)*64 + i]
// ---------------------------------------------------------------------------
__global__ __launch_bounds__(256) void wsplit_kernel(const float* __restrict__ w) {
    __shared__ float sw[64 * 64];
    int hc = blockIdx.x;                       // h*NK + c
    const float4* wg = (const float4*)(w + (size_t)hc * 4096);
    for (int idx = threadIdx.x; idx < 1024; idx += 256)
        ((float4*)sw)[idx] = wg[idx];
    __syncthreads();

    int o = threadIdx.x >> 2, q = threadIdx.x & 3;   // q = i-quarter of 16
    __nv_bfloat16 hi[16], lo[16];
#pragma unroll
    for (int j = 0; j < 16; j++) {
        float v = sw[(q * 16 + j) * 64 + o];          // w[h][c][i][o]
        __nv_bfloat16 hb = __float2bfloat16_rn(v);
        hi[j] = hb;
        lo[j] = __float2bfloat16_rn(v - __bfloat162float(hb));
    }
    size_t base = ((size_t)hc * 64 + o) * 64 + q * 16;
    *(uint4*)(g_bhi + base)     = ((uint4*)hi)[0];
    *(uint4*)(g_bhi + base + 8) = ((uint4*)hi)[1];
    *(uint4*)(g_blo + base)     = ((uint4*)lo)[0];
    *(uint4*)(g_blo + base + 8) = ((uint4*)lo)[1];
}

// ---------------------------------------------------------------------------
// Kernel 1: scores[m,k] = phi[t,k] + sum_i x[m,i] * diag[k,i]
// ---------------------------------------------------------------------------
__global__ __launch_bounds__(256) void scores_kernel(
        const float* __restrict__ x, const float* __restrict__ diag,
        const float* __restrict__ phi, int M, int T) {
    __shared__ float sdiag[NK * D_IN];
    int tid = threadIdx.x;
    for (int idx = tid; idx < NK * D_IN / 4; idx += 256)
        ((float4*)sdiag)[idx] = ((const float4*)diag)[idx];
    __syncthreads();

    int warp = tid >> 5, lane = tid & 31;
    int m = blockIdx.x * 8 + warp;
    if (m >= M) return;

    const float4* xr = (const float4*)(x + (size_t)m * D_IN);
    float acc[NK];
#pragma unroll
    for (int k = 0; k < NK; k++) acc[k] = 0.f;
#pragma unroll
    for (int j = 0; j < 8; j++) {
        float4 xv = xr[j * 32 + lane];
#pragma unroll
        for (int k = 0; k < NK; k++) {
            float4 dv = *(const float4*)&sdiag[k * D_IN + j * 128 + lane * 4];
            acc[k] += xv.x * dv.x + xv.y * dv.y + xv.z * dv.z + xv.w * dv.w;
        }
    }
#pragma unroll
    for (int k = 0; k < NK; k++)
#pragma unroll
        for (int off = 16; off; off >>= 1)
            acc[k] += __shfl_xor_sync(0xffffffffu, acc[k], off);
    if (lane < NK) {
        float v = 0.f;
#pragma unroll
        for (int k = 0; k < NK; k++)
            if (lane == k) v = acc[k];
        int t = m % T;
        g_scores[m * NK + lane] = phi[t * NK + lane] + v;
    }
}

// ---------------------------------------------------------------------------
// Main: per (256-token tile, head). 256 threads, 8 warps; warp = m32 x n64.
//   P_c = X . B_c^T (3-pass bf16 split, X frags register-resident, loaded once)
//   acc += s[m,c] * P_c   (fp32 epilogue scaling)
// No syncthreads in the chunk loop. XOR-swizzled 128B smem rows.
// smem: Bhi 64K | Blo 64K | Xhi 32K | Xlo 32K | scores 8K = 200 KB.
// ---------------------------------------------------------------------------
#define SB_HI 0
#define SB_LO 65536
#define SX_HI 131072
#define SX_LO 163840
#define SS    196608
#define SMEM_TOTAL 204800

__global__ __launch_bounds__(256, 1) void main_kernel(
        const float* __restrict__ x, float* __restrict__ out) {
    extern __shared__ char sm[];
    int tid  = threadIdx.x;
    int lane = tid & 31, wid = tid >> 5;
    int h    = blockIdx.y;
    int m0   = blockIdx.x * MT;

    // --- B copy (linear read, swizzled store; 16B granules)
    {
        const uint4* gh = (const uint4*)(g_bhi + (size_t)h * NK * 64 * 64);
        const uint4* gl = (const uint4*)(g_blo + (size_t)h * NK * 64 * 64);
        for (int i = tid; i < 4096; i += 256) {
            uint32_t byte = i * 16;
            uint32_t dst  = (byte & ~127u) | ((byte & 127u) ^ (((byte >> 7) & 7u) << 4));
            *(uint4*)(sm + SB_HI + dst) = gh[i];
            *(uint4*)(sm + SB_LO + dst) = gl[i];
        }
    }
    // --- X split hi/lo (thread per row)
    {
        int r = tid;
        const float4* xp = (const float4*)(x + (size_t)(m0 + r) * D_IN + h * D_H);
        uint32_t rsw = (uint32_t)(r & 7) << 4;
#pragma unroll
        for (int j = 0; j < 8; j++) {
            float4 v0 = xp[2 * j], v1 = xp[2 * j + 1];
            float vv[8] = {v0.x, v0.y, v0.z, v0.w, v1.x, v1.y, v1.z, v1.w};
            __nv_bfloat16 hb[8], lb[8];
#pragma unroll
            for (int e = 0; e < 8; e++) {
                hb[e] = __float2bfloat16_rn(vv[e]);
                lb[e] = __float2bfloat16_rn(vv[e] - __bfloat162float(hb[e]));
            }
            uint32_t dst = r * 128 + ((uint32_t)(j * 16) ^ rsw);
            *(uint4*)(sm + SX_HI + dst) = *(uint4*)hb;
            *(uint4*)(sm + SX_LO + dst) = *(uint4*)lb;
        }
    }
    // --- scores tile
    {
        float* ssp = (float*)(sm + SS);
        const float* gs = g_scores + (size_t)m0 * NK;
        for (int i = tid; i < MT * NK; i += 256) ssp[i] = gs[i];
    }
    __syncthreads();

    // --- load X fragments (once)
    int a_r = lane & 15;
    uint32_t a_c = (uint32_t)((lane >> 4) * 16);
    uint32_t xbase = smem_u32(sm);
    uint32_t xh[2][4][4], xl[2][4][4];
#pragma unroll
    for (int mb = 0; mb < 2; mb++) {
        int row = wid * 32 + mb * 16 + a_r;
        uint32_t rsw = (uint32_t)(row & 7) << 4;
#pragma unroll
        for (int ks = 0; ks < 4; ks++) {
            uint32_t off = row * 128 + (((uint32_t)(ks * 32) + a_c) ^ rsw);
            ldmx4(xh[mb][ks], xbase + SX_HI + off);
            ldmx4(xl[mb][ks], xbase + SX_LO + off);
        }
    }

    // --- B lane address components
    int b_r = (lane & 7) + ((lane >> 4) & 1) * 8;
    uint32_t b_c = (uint32_t)(((lane >> 3) & 1) * 16);
    uint32_t brsw = (uint32_t)(b_r & 7) << 4;
    uint32_t bcol[4];
#pragma unroll
    for (int ks = 0; ks < 4; ks++)
        bcol[ks] = (((uint32_t)(ks * 32) + b_c) ^ brsw);

    float acc[2][4][2][4];
#pragma unroll
    for (int mb = 0; mb < 2; mb++)
#pragma unroll
        for (int p = 0; p < 4; p++)
#pragma unroll
            for (int nb = 0; nb < 2; nb++)
#pragma unroll
                for (int e = 0; e < 4; e++) acc[mb][p][nb][e] = 0.f;

    const float* ssp = (const float*)(sm + SS);
    int er0 = wid * 32 + (lane >> 2);          // epilogue row base (mb=0)

#pragma unroll 1
    for (int c = 0; c < NK; c++) {
        uint32_t bch = xbase + SB_HI + c * 8192;
        uint32_t bcl = xbase + SB_LO + c * 8192;
#pragma unroll
        for (int p = 0; p < 4; p++) {
            float P[2][2][4];
#pragma unroll
            for (int mb = 0; mb < 2; mb++)
#pragma unroll
                for (int nb = 0; nb < 2; nb++)
#pragma unroll
                    for (int e = 0; e < 4; e++) P[mb][nb][e] = 0.f;

            uint32_t brow = (uint32_t)((p * 16 + b_r) * 128);
#pragma unroll
            for (int ks = 0; ks < 4; ks++) {
                uint32_t bh[4], bl[4];
                ldmx4(bh, bch + brow + bcol[ks]);
                ldmx4(bl, bcl + brow + bcol[ks]);
#pragma unroll
                for (int mb = 0; mb < 2; mb++)
#pragma unroll
                    for (int nb = 0; nb < 2; nb++) {
                        float* d = P[mb][nb];
                        mma16816(d, xh[mb][ks], bh + 2 * nb);
                        mma16816(d, xh[mb][ks], bl + 2 * nb);
                        mma16816(d, xl[mb][ks], bh + 2 * nb);
                    }
            }
            // epilogue: acc += s * P
#pragma unroll
            for (int mb = 0; mb < 2; mb++) {
                int r0 = er0 + mb * 16;
                float s0 = ssp[r0 * NK + c];
                float s1 = ssp[(r0 + 8) * NK + c];
#pragma unroll
                for (int nb = 0; nb < 2; nb++) {
                    acc[mb][p][nb][0] += s0 * P[mb][nb][0];
                    acc[mb][p][nb][1] += s0 * P[mb][nb][1];
                    acc[mb][p][nb][2] += s1 * P[mb][nb][2];
                    acc[mb][p][nb][3] += s1 * P[mb][nb][3];
                }
            }
        }
    }

    // --- store
#pragma unroll
    for (int mb = 0; mb < 2; mb++) {
        int m = m0 + wid * 32 + mb * 16 + (lane >> 2);
        float* o0 = out + (size_t)m * D_IN + h * D_H + (lane & 3) * 2;
#pragma unroll
        for (int p = 0; p < 4; p++)
#pragma unroll
            for (int nb = 0; nb < 2; nb++) {
                float2 v0 = make_float2(acc[mb][p][nb][0], acc[mb][p][nb][1]);
                float2 v1 = make_float2(acc[mb][p][nb][2], acc[mb][p][nb][3]);
                *(float2*)(o0 + p * 16 + nb * 8)                     = v0;
                *(float2*)(o0 + p * 16 + nb * 8 + 8 * (size_t)D_IN) = v1;
            }
    }
}

// ---------------------------------------------------------------------------
extern "C" void kernel_launch(void* const* d_in, const int* in_sizes, int n_in,
                              void* d_out, int out_size) {
    const float* x      = (const float*)d_in[0];
    const float* weight = (const float*)d_in[1];
    const float* diag   = (const float*)d_in[2];
    const float* phi    = (const float*)d_in[3];
    float* out          = (float*)d_out;

    int M = in_sizes[0] / D_IN;   // B*T tokens
    int T = in_sizes[3] / NK;     // phi rows

    cudaFuncSetAttribute(main_kernel,
                         cudaFuncAttributeMaxDynamicSharedMemorySize, SMEM_TOTAL);

    wsplit_kernel<<<NH * NK, 256>>>(weight);
    scores_kernel<<<(M + 7) / 8, 256>>>(x, diag, phi, M, T);

    dim3 grid(M / MT, NH);
    main_kernel<<<grid, 256, SMEM_TOTAL>>>(x, out);
}